// round 16
// baseline (speedup 1.0000x reference)
#include <cuda_runtime.h>
#include <cuda_fp16.h>
#include <cuda_bf16.h>

// HashEncoder: 4-level dense-grid trilinear interpolation, F=4.
// R16 = R14 encode VERBATIM (best measured: 62.7us encode, regs=30, occ 86%)
//     + per-cell build_cells (1 thread/cell: 8x LDG.128 corner reads,
//       4x STG.128 contiguous 64B record write — half the load instructions
//       of the 2-thread/cell version).
// fp16 cell records (64B/cell, values pre-scaled by 2^12). Per (cell,feature):
// 4 half2 groups g(dy*2+dx) = {c(dx,dy,z0), c(dx,dy,z1)}.
// Encode: 2 points per warp-slot (lane = q*16 + L*4 + f); ONE 16B gather per
// lane per slot -> 4 L1tex wavefronts/point (gather optimum). Depth-1
// position prefetch under __launch_bounds__(256,7) reg cap. Positions __ldcs,
// output __stcs (protects cell table's L2 residency).
//
// Level meta: res={32,43,56,74}, offsets={0,32768,112280,287896}, total=693120.

#define NPARAMS 693120
#define VAL_SCALE 4096.0f
#define INV_VAL_SCALE (1.0f / 4096.0f)

__device__ __half g_cells_h[NPARAMS * 32];   // 44.4 MB scratch (64B/cell)

__constant__ int c_res[4] = {32, 43, 56, 74};
__constant__ int c_off[4] = {0, 32768, 112280, 287896};

// ---------------------------------------------------------------- preprocess table
// thread t = gbase : builds the full 64B record of one cell.
// Reads 8 float4 (all 4 features of each corner), writes 4 uint4 (64B).
__global__ void __launch_bounds__(256)
build_cells(const float* __restrict__ tab)
{
    int gbase = blockIdx.x * blockDim.x + threadIdx.x;
    if (gbase >= NPARAMS) return;

    int L = (gbase >= 32768) + (gbase >= 112280) + (gbase >= 287896);
    int res  = c_res[L];
    int off  = c_off[L];
    int res2 = res * res;
    int local = gbase - off;

    int z   = local / res2;          // padding cells may exceed grid; clamp below
    int rem = local - z * res2;
    int y   = rem / res;
    int x   = rem - y * res;

    // c[g][dz] = float4 of all 4 features at corner (dx,dy,dz), g = dy*2+dx
    float4 c[4][2];
#pragma unroll
    for (int g = 0; g < 4; ++g) {
        int xi = min(x + (g & 1), res - 1);
        int yi = min(y + (g >> 1), res - 1);
#pragma unroll
        for (int dz = 0; dz < 2; ++dz) {
            int zi = min(z + dz, res - 1);
            int idx = off + xi + yi * res + zi * res2;
            float4 w = __ldg((const float4*)&tab[idx * 4]);
            c[g][dz] = make_float4(w.x * VAL_SCALE, w.y * VAL_SCALE,
                                   w.z * VAL_SCALE, w.w * VAL_SCALE);
        }
    }

    // Record for feature f: group g = half2( c[g][0].f , c[g][1].f ).
    uint4 recs[4];
#pragma unroll
    for (int f = 0; f < 4; ++f) {
        float v00 = (f == 0) ? c[0][0].x : (f == 1) ? c[0][0].y : (f == 2) ? c[0][0].z : c[0][0].w;
        float v01 = (f == 0) ? c[0][1].x : (f == 1) ? c[0][1].y : (f == 2) ? c[0][1].z : c[0][1].w;
        float v10 = (f == 0) ? c[1][0].x : (f == 1) ? c[1][0].y : (f == 2) ? c[1][0].z : c[1][0].w;
        float v11 = (f == 0) ? c[1][1].x : (f == 1) ? c[1][1].y : (f == 2) ? c[1][1].z : c[1][1].w;
        float v20 = (f == 0) ? c[2][0].x : (f == 1) ? c[2][0].y : (f == 2) ? c[2][0].z : c[2][0].w;
        float v21 = (f == 0) ? c[2][1].x : (f == 1) ? c[2][1].y : (f == 2) ? c[2][1].z : c[2][1].w;
        float v30 = (f == 0) ? c[3][0].x : (f == 1) ? c[3][0].y : (f == 2) ? c[3][0].z : c[3][0].w;
        float v31 = (f == 0) ? c[3][1].x : (f == 1) ? c[3][1].y : (f == 2) ? c[3][1].z : c[3][1].w;
        half2 h0 = __floats2half2_rn(v00, v01);
        half2 h1 = __floats2half2_rn(v10, v11);
        half2 h2 = __floats2half2_rn(v20, v21);
        half2 h3 = __floats2half2_rn(v30, v31);
        recs[f].x = *(unsigned*)&h0;
        recs[f].y = *(unsigned*)&h1;
        recs[f].z = *(unsigned*)&h2;
        recs[f].w = *(unsigned*)&h3;
    }

    uint4* dst = (uint4*)g_cells_h + (size_t)gbase * 4;
    dst[0] = recs[0];
    dst[1] = recs[1];
    dst[2] = recs[2];
    dst[3] = recs[3];
}

// ---------------------------------------------------------------- main pass
// R14 encode, verbatim.
__device__ __forceinline__ void
encode_fast(const float* __restrict__ pos, float* __restrict__ out,
            const __half* __restrict__ cells_f, float s,
            int res, int res2, int off,
            int p0, int q, int lane)
{
    const float* pp = pos + 3 * (p0 + q);      // this lane's first point
    float nx = __ldcs(&pp[0]);
    float ny = __ldcs(&pp[1]);
    float nz = __ldcs(&pp[2]);

#pragma unroll
    for (int k = 0; k < 8; ++k) {
        float x = nx, y = ny, z = nz;
        if (k < 7) {                           // prefetch next slot's position
            nx = __ldcs(&pp[6 * (k + 1) + 0]);
            ny = __ldcs(&pp[6 * (k + 1) + 1]);
            nz = __ldcs(&pp[6 * (k + 1) + 2]);
        }

        float px = fmaf(x, s, 0.5f);
        float py = fmaf(y, s, 0.5f);
        float pz = fmaf(z, s, 0.5f);
        int ix = __float2int_rd(px);           // px,py,pz >= 0.5: rd == floor
        int iy = __float2int_rd(py);
        int iz = __float2int_rd(pz);
        float fx = px - __int2float_rn(ix);
        float fy = py - __int2float_rn(iy);
        float fz = pz - __int2float_rn(iz);

        int gbase = off + ix + iy * res + iz * res2;

        uint4 rec = __ldg((const uint4*)(cells_f + (size_t)gbase * 32));
        half2 g0 = *(half2*)&rec.x;            // (dx,dy)=(0,0), {z0,z1}
        half2 g1 = *(half2*)&rec.y;            // (1,0)
        half2 g2 = *(half2*)&rec.z;            // (0,1)
        half2 g3 = *(half2*)&rec.w;            // (1,1)

        half2 fx2 = __float2half2_rn(fx);
        half2 fy2 = __float2half2_rn(fy);

        half2 a = __hfma2(fx2, __hsub2(g1, g0), g0);
        half2 b = __hfma2(fx2, __hsub2(g3, g2), g2);
        half2 c = __hfma2(fy2, __hsub2(b, a), a);    // {z0, z1}

        float clo = __low2float(c);
        float chi = __high2float(c);
        float r = fmaf(fz, chi - clo, clo) * INV_VAL_SCALE;

        __stcs(&out[(size_t)p0 * 16 + 32 * k + lane], r);
    }
}

// Guard path (tail warp only; never taken when n % 16 == 0).
__device__ __forceinline__ void
encode_guard(const float* __restrict__ pos, float* __restrict__ out,
             const __half* __restrict__ cells_f, float s,
             int res, int res2, int off,
             int p0, int q, int lane, int n)
{
    for (int k = 0; k < 8; ++k) {
        int p = p0 + 2 * k + q;
        bool valid = (p < n);
        int pc = valid ? p : (n - 1);

        float x = __ldcs(&pos[3 * pc + 0]);
        float y = __ldcs(&pos[3 * pc + 1]);
        float z = __ldcs(&pos[3 * pc + 2]);

        float px = fmaf(x, s, 0.5f);
        float py = fmaf(y, s, 0.5f);
        float pz = fmaf(z, s, 0.5f);
        int ix = __float2int_rd(px);
        int iy = __float2int_rd(py);
        int iz = __float2int_rd(pz);
        float fx = px - __int2float_rn(ix);
        float fy = py - __int2float_rn(iy);
        float fz = pz - __int2float_rn(iz);

        int gbase = off + ix + iy * res + iz * res2;

        uint4 rec = __ldg((const uint4*)(cells_f + (size_t)gbase * 32));
        half2 g0 = *(half2*)&rec.x;
        half2 g1 = *(half2*)&rec.y;
        half2 g2 = *(half2*)&rec.z;
        half2 g3 = *(half2*)&rec.w;

        half2 fx2 = __float2half2_rn(fx);
        half2 fy2 = __float2half2_rn(fy);

        half2 a = __hfma2(fx2, __hsub2(g1, g0), g0);
        half2 b = __hfma2(fx2, __hsub2(g3, g2), g2);
        half2 c = __hfma2(fy2, __hsub2(b, a), a);

        float clo = __low2float(c);
        float chi = __high2float(c);
        float r = fmaf(fz, chi - clo, clo) * INV_VAL_SCALE;

        if (valid)
            __stcs(&out[(size_t)p0 * 16 + 32 * k + lane], r);
    }
}

__global__ void __launch_bounds__(256, 7)   // caps regs at 36: keeps 56 warps/SM
encode_kernel(const float* __restrict__ pos, float* __restrict__ out,
              float4 scales, int n)
{
    const int lane = threadIdx.x & 31;
    const int warp = (blockIdx.x * blockDim.x + threadIdx.x) >> 5;
    const int p0 = warp * 16;
    if (p0 >= n) return;

    const int q = lane >> 4;            // point parity within slot
    const int L = (lane >> 2) & 3;      // level
    const int f = lane & 3;             // feature

    const float s = (L < 2) ? (L == 0 ? scales.x : scales.y)
                            : (L == 2 ? scales.z : scales.w);
    const int res  = c_res[L];
    const int res2 = res * res;
    const int off  = c_off[L];
    const __half* cells_f = g_cells_h + f * 8;

    if (p0 + 16 <= n)
        encode_fast(pos, out, cells_f, s, res, res2, off, p0, q, lane);
    else
        encode_guard(pos, out, cells_f, s, res, res2, off, p0, q, lane, n);
}

// ---------------------------------------------------------------- launcher
extern "C" void kernel_launch(void* const* d_in, const int* in_sizes, int n_in,
                              void* d_out, int out_size)
{
    const float* positions = (const float*)d_in[0];
    const float* table = (const float*)d_in[1];
    float* out = (float*)d_out;

    int n = in_sizes[0] / 3;

    // Level scales: double math, rounded to fp32 like JAX's weak promotion.
    double b = 1.3195079565048218;
    double p = 1.0;
    float s[4];
    for (int l = 0; l < 4; ++l) {
        s[l] = (float)(32.0 * p - 1.0);
        p *= b;
    }
    float4 scales = make_float4(s[0], s[1], s[2], s[3]);

    int bb = (NPARAMS + 255) / 256;
    build_cells<<<bb, 256>>>(table);

    int warps = (n + 15) / 16;
    int blocks = (warps * 32 + 255) / 256;
    encode_kernel<<<blocks, 256>>>(positions, out, scales, n);
}

// round 17
// speedup vs baseline: 1.0319x; 1.0319x over previous
#include <cuda_runtime.h>
#include <cuda_fp16.h>
#include <cuda_bf16.h>

// HashEncoder: 4-level dense-grid trilinear interpolation, F=4.
// R17 = R14 encode with __launch_bounds__(256,8) (regs already 30 <= 32, so
// the tighter cap costs nothing and lifts residency 56 -> 64 warps/SM)
//     + R8 feature-pair build_cells (best measured: 11.5us).
// fp16 cell records (64B/cell, values pre-scaled by 2^12). Per (cell,feature):
// 4 half2 groups g(dy*2+dx) = {c(dx,dy,z0), c(dx,dy,z1)}.
// Encode: 2 points per warp-slot (lane = q*16 + L*4 + f); ONE 16B gather per
// lane per slot -> 4 L1tex wavefronts/point (gather optimum). Depth-1
// position prefetch. Positions __ldcs, output __stcs (protects the cell
// table's L2 residency).
//
// Level meta: res={32,43,56,74}, offsets={0,32768,112280,287896}, total=693120.

#define NPARAMS 693120
#define VAL_SCALE 4096.0f
#define INV_VAL_SCALE (1.0f / 4096.0f)

__device__ __half g_cells_h[NPARAMS * 32];   // 44.4 MB scratch (64B/cell)

__constant__ int c_res[4] = {32, 43, 56, 74};
__constant__ int c_off[4] = {0, 32768, 112280, 287896};

// ---------------------------------------------------------------- preprocess table
// thread t = gbase*2 + fp : builds records for features {2fp, 2fp+1}.
// (R8 version — best measured. 2 threads/cell keeps live state small and
// thread count high; the 1-thread/cell variant regressed via ILP/occupancy.)
__global__ void __launch_bounds__(256)
build_cells(const float* __restrict__ tab)
{
    int t = blockIdx.x * blockDim.x + threadIdx.x;
    if (t >= NPARAMS * 2) return;

    int gbase = t >> 1;
    int fp = t & 1;

    int L = (gbase >= 32768) + (gbase >= 112280) + (gbase >= 287896);
    int res  = c_res[L];
    int off  = c_off[L];
    int res2 = res * res;
    int local = gbase - off;

    int z   = local / res2;          // padding cells may exceed grid; clamp below
    int rem = local - z * res2;
    int y   = rem / res;
    int x   = rem - y * res;

    float2 v[4][2];                  // [g=dy*2+dx][dz] = (feat 2fp, feat 2fp+1)
#pragma unroll
    for (int g = 0; g < 4; ++g) {
        int xi = min(x + (g & 1), res - 1);
        int yi = min(y + (g >> 1), res - 1);
#pragma unroll
        for (int dz = 0; dz < 2; ++dz) {
            int zi = min(z + dz, res - 1);
            int idx = off + xi + yi * res + zi * res2;
            float2 w = __ldg((const float2*)&tab[idx * 4 + 2 * fp]);
            v[g][dz] = make_float2(w.x * VAL_SCALE, w.y * VAL_SCALE);
        }
    }

    uint4 r0, r1;
    {
        half2 h0 = __floats2half2_rn(v[0][0].x, v[0][1].x);
        half2 h1 = __floats2half2_rn(v[1][0].x, v[1][1].x);
        half2 h2 = __floats2half2_rn(v[2][0].x, v[2][1].x);
        half2 h3 = __floats2half2_rn(v[3][0].x, v[3][1].x);
        r0.x = *(unsigned*)&h0; r0.y = *(unsigned*)&h1;
        r0.z = *(unsigned*)&h2; r0.w = *(unsigned*)&h3;
    }
    {
        half2 h0 = __floats2half2_rn(v[0][0].y, v[0][1].y);
        half2 h1 = __floats2half2_rn(v[1][0].y, v[1][1].y);
        half2 h2 = __floats2half2_rn(v[2][0].y, v[2][1].y);
        half2 h3 = __floats2half2_rn(v[3][0].y, v[3][1].y);
        r1.x = *(unsigned*)&h0; r1.y = *(unsigned*)&h1;
        r1.z = *(unsigned*)&h2; r1.w = *(unsigned*)&h3;
    }

    uint4* dst = (uint4*)g_cells_h;
    dst[gbase * 4 + 2 * fp]     = r0;
    dst[gbase * 4 + 2 * fp + 1] = r1;
}

// ---------------------------------------------------------------- main pass
// R14 encode, verbatim except the launch-bounds cap.
__device__ __forceinline__ void
encode_fast(const float* __restrict__ pos, float* __restrict__ out,
            const __half* __restrict__ cells_f, float s,
            int res, int res2, int off,
            int p0, int q, int lane)
{
    const float* pp = pos + 3 * (p0 + q);      // this lane's first point
    float nx = __ldcs(&pp[0]);
    float ny = __ldcs(&pp[1]);
    float nz = __ldcs(&pp[2]);

#pragma unroll
    for (int k = 0; k < 8; ++k) {
        float x = nx, y = ny, z = nz;
        if (k < 7) {                           // prefetch next slot's position
            nx = __ldcs(&pp[6 * (k + 1) + 0]);
            ny = __ldcs(&pp[6 * (k + 1) + 1]);
            nz = __ldcs(&pp[6 * (k + 1) + 2]);
        }

        float px = fmaf(x, s, 0.5f);
        float py = fmaf(y, s, 0.5f);
        float pz = fmaf(z, s, 0.5f);
        int ix = __float2int_rd(px);           // px,py,pz >= 0.5: rd == floor
        int iy = __float2int_rd(py);
        int iz = __float2int_rd(pz);
        float fx = px - __int2float_rn(ix);
        float fy = py - __int2float_rn(iy);
        float fz = pz - __int2float_rn(iz);

        int gbase = off + ix + iy * res + iz * res2;

        uint4 rec = __ldg((const uint4*)(cells_f + (size_t)gbase * 32));
        half2 g0 = *(half2*)&rec.x;            // (dx,dy)=(0,0), {z0,z1}
        half2 g1 = *(half2*)&rec.y;            // (1,0)
        half2 g2 = *(half2*)&rec.z;            // (0,1)
        half2 g3 = *(half2*)&rec.w;            // (1,1)

        half2 fx2 = __float2half2_rn(fx);
        half2 fy2 = __float2half2_rn(fy);

        half2 a = __hfma2(fx2, __hsub2(g1, g0), g0);
        half2 b = __hfma2(fx2, __hsub2(g3, g2), g2);
        half2 c = __hfma2(fy2, __hsub2(b, a), a);    // {z0, z1}

        float clo = __low2float(c);
        float chi = __high2float(c);
        float r = fmaf(fz, chi - clo, clo) * INV_VAL_SCALE;

        __stcs(&out[(size_t)p0 * 16 + 32 * k + lane], r);
    }
}

// Guard path (tail warp only; never taken when n % 16 == 0).
__device__ __forceinline__ void
encode_guard(const float* __restrict__ pos, float* __restrict__ out,
             const __half* __restrict__ cells_f, float s,
             int res, int res2, int off,
             int p0, int q, int lane, int n)
{
    for (int k = 0; k < 8; ++k) {
        int p = p0 + 2 * k + q;
        bool valid = (p < n);
        int pc = valid ? p : (n - 1);

        float x = __ldcs(&pos[3 * pc + 0]);
        float y = __ldcs(&pos[3 * pc + 1]);
        float z = __ldcs(&pos[3 * pc + 2]);

        float px = fmaf(x, s, 0.5f);
        float py = fmaf(y, s, 0.5f);
        float pz = fmaf(z, s, 0.5f);
        int ix = __float2int_rd(px);
        int iy = __float2int_rd(py);
        int iz = __float2int_rd(pz);
        float fx = px - __int2float_rn(ix);
        float fy = py - __int2float_rn(iy);
        float fz = pz - __int2float_rn(iz);

        int gbase = off + ix + iy * res + iz * res2;

        uint4 rec = __ldg((const uint4*)(cells_f + (size_t)gbase * 32));
        half2 g0 = *(half2*)&rec.x;
        half2 g1 = *(half2*)&rec.y;
        half2 g2 = *(half2*)&rec.z;
        half2 g3 = *(half2*)&rec.w;

        half2 fx2 = __float2half2_rn(fx);
        half2 fy2 = __float2half2_rn(fy);

        half2 a = __hfma2(fx2, __hsub2(g1, g0), g0);
        half2 b = __hfma2(fx2, __hsub2(g3, g2), g2);
        half2 c = __hfma2(fy2, __hsub2(b, a), a);

        float clo = __low2float(c);
        float chi = __high2float(c);
        float r = fmaf(fz, chi - clo, clo) * INV_VAL_SCALE;

        if (valid)
            __stcs(&out[(size_t)p0 * 16 + 32 * k + lane], r);
    }
}

__global__ void __launch_bounds__(256, 8)   // 32-reg budget; current code = 30
encode_kernel(const float* __restrict__ pos, float* __restrict__ out,
              float4 scales, int n)
{
    const int lane = threadIdx.x & 31;
    const int warp = (blockIdx.x * blockDim.x + threadIdx.x) >> 5;
    const int p0 = warp * 16;
    if (p0 >= n) return;

    const int q = lane >> 4;            // point parity within slot
    const int L = (lane >> 2) & 3;      // level
    const int f = lane & 3;             // feature

    const float s = (L < 2) ? (L == 0 ? scales.x : scales.y)
                            : (L == 2 ? scales.z : scales.w);
    const int res  = c_res[L];
    const int res2 = res * res;
    const int off  = c_off[L];
    const __half* cells_f = g_cells_h + f * 8;

    if (p0 + 16 <= n)
        encode_fast(pos, out, cells_f, s, res, res2, off, p0, q, lane);
    else
        encode_guard(pos, out, cells_f, s, res, res2, off, p0, q, lane, n);
}

// ---------------------------------------------------------------- launcher
extern "C" void kernel_launch(void* const* d_in, const int* in_sizes, int n_in,
                              void* d_out, int out_size)
{
    const float* positions = (const float*)d_in[0];
    const float* table = (const float*)d_in[1];
    float* out = (float*)d_out;

    int n = in_sizes[0] / 3;

    // Level scales: double math, rounded to fp32 like JAX's weak promotion.
    double b = 1.3195079565048218;
    double p = 1.0;
    float s[4];
    for (int l = 0; l < 4; ++l) {
        s[l] = (float)(32.0 * p - 1.0);
        p *= b;
    }
    float4 scales = make_float4(s[0], s[1], s[2], s[3]);

    int bb = (NPARAMS * 2 + 255) / 256;
    build_cells<<<bb, 256>>>(table);

    int warps = (n + 15) / 16;
    int blocks = (warps * 32 + 255) / 256;
    encode_kernel<<<blocks, 256>>>(positions, out, scales, n);
}